// round 9
// baseline (speedup 1.0000x reference)
#include <cuda_runtime.h>
#include <cuda_bf16.h>
#include <stdint.h>

// CorrAttentionBias: out[b,h,i,j] = (mask[b,i]||mask[b,j]) ? -1e5
//   : attn[b,h,i,j] + BETA*c_sink[b,i]*c_sink[b,j] + ALPHA*edge(b,i,j)*(|i-j|==1)
// where edge(b,i,j): j=i+1 -> c_local[b,j];
//                    j=i-1 -> c_local[b,i-1] for 2<=i<=L-2, else c_local[b,i]
// (the two overlapping .at[].set() calls in the reference overwrite each other;
//  the border rows i=1 and i=L-1 keep the FIRST assignment's value.)
//
// B=2, H=16, L=2048. Pure HBM-streaming elementwise.

#define ALPHA 0.5f
#define BETA  0.1f
#define NEGV  (-100000.0f)

constexpr int L   = 2048;
constexpr int H   = 16;
constexpr int TPB = 512;   // 512 threads * float4 = 2048 columns
constexpr int MASK_MAX = 4096;

// normalized mask (1 byte per element), filled by prepass
__device__ unsigned char g_mask[MASK_MAX];

// Prepass: the harness ships only {float32,int32,bf16}; a bool mask is most
// likely int32, but detect byte-packed bools too. Interpreting the buffer as
// int32: if every one of the first n/4 words is 0 or 1 -> int32 encoding
// (byte-packed random bools would almost surely form words like 0x00010100).
// Reading n/4 words is in-bounds under either encoding (n/4 words == n bytes).
__global__ void normalize_mask_kernel(const void* __restrict__ mraw, int n)
{
    __shared__ int s_nonbinary;
    const int tid = threadIdx.x;
    if (tid == 0) s_nonbinary = 0;
    __syncthreads();

    const int* wi = (const int*)mraw;
    const int nwords_probe = n / 4;
    for (int k = tid; k < nwords_probe; k += blockDim.x) {
        unsigned int w = (unsigned int)wi[k];
        if (w > 1u) atomicOr(&s_nonbinary, 1);
    }
    __syncthreads();

    if (s_nonbinary) {
        // byte-packed bools
        const unsigned char* mb = (const unsigned char*)mraw;
        for (int k = tid; k < n; k += blockDim.x)
            g_mask[k] = mb[k] ? 1 : 0;
    } else {
        // int32 words
        for (int k = tid; k < n; k += blockDim.x)
            g_mask[k] = wi[k] ? 1 : 0;
    }
}

__global__ __launch_bounds__(TPB, 4) void corr_bias_kernel(
    const float* __restrict__ attn,
    const float* __restrict__ c_local,
    const float* __restrict__ c_sink,
    float* __restrict__ out)
{
    const int r   = blockIdx.x;          // r = b*L + i
    const int b   = r >> 11;             // / L
    const int i   = r & (L - 1);
    const int tid = threadIdx.x;

    const size_t HL      = (size_t)L * (size_t)L;
    const size_t rowbase = (size_t)b * H * HL + (size_t)i * L;

    // ---- fast path: whole (i) row is NEG for every head; attn never read ----
    if (g_mask[b * L + i]) {
        const float4 negv = make_float4(NEGV, NEGV, NEGV, NEGV);
        #pragma unroll
        for (int h = 0; h < H; h++) {
            reinterpret_cast<float4*>(out + rowbase + (size_t)h * HL)[tid] = negv;
        }
        return;
    }

    // ---- per-thread bias for columns j0..j0+3, computed once ----
    const int   j0 = tid * 4;
    const int   bL = b * L;
    const float si = BETA * c_sink[bL + i];

    const float4 cs = reinterpret_cast<const float4*>(c_sink + (size_t)bL)[tid];
    const uchar4 mk = reinterpret_cast<const uchar4*>(g_mask + bL)[tid];

    float bz[4] = { si * cs.x, si * cs.y, si * cs.z, si * cs.w };

    #pragma unroll
    for (int q = 0; q < 4; q++) {
        const int j = j0 + q;
        if (j == i + 1) {
            bz[q] += ALPHA * c_local[bL + j];
        } else if (j == i - 1) {
            // interior rows take the 2nd .set() value c_local[b,i-1];
            // border rows i=1 and i=L-1 keep the 1st .set() value c_local[b,i]
            const int src = (i >= 2 && i <= L - 2) ? (i - 1) : i;
            bz[q] += ALPHA * c_local[bL + src];
        }
    }

    const unsigned char m0 = mk.x, m1 = mk.y, m2 = mk.z, m3 = mk.w;

    // ---- stream 16 head-rows; bias/mask live in registers ----
    #pragma unroll 4
    for (int h = 0; h < H; h++) {
        const float4 a = reinterpret_cast<const float4*>(attn + rowbase + (size_t)h * HL)[tid];
        float4 o;
        o.x = m0 ? NEGV : a.x + bz[0];
        o.y = m1 ? NEGV : a.y + bz[1];
        o.z = m2 ? NEGV : a.z + bz[2];
        o.w = m3 ? NEGV : a.w + bz[3];
        reinterpret_cast<float4*>(out + rowbase + (size_t)h * HL)[tid] = o;
    }
}

extern "C" void kernel_launch(void* const* d_in, const int* in_sizes, int n_in,
                              void* d_out, int out_size)
{
    const float* attn    = (const float*)d_in[0];
    const float* c_local = (const float*)d_in[1];
    const float* c_sink  = (const float*)d_in[2];
    const void*  mraw    = d_in[3];
    float*       out     = (float*)d_out;

    const int n_mask = in_sizes[3];   // B * L = 4096
    normalize_mask_kernel<<<1, 1024>>>(mraw, n_mask);

    const int n_rows = in_sizes[1];   // B * L
    corr_bias_kernel<<<n_rows, TPB>>>(attn, c_local, c_sink, out);
}

// round 13
// speedup vs baseline: 1.0194x; 1.0194x over previous
#include <cuda_runtime.h>
#include <cuda_bf16.h>
#include <stdint.h>

// CorrAttentionBias: out[b,h,i,j] = (mask[b,i]||mask[b,j]) ? -1e5
//   : attn[b,h,i,j] + BETA*c_sink[b,i]*c_sink[b,j] + ALPHA*edge(b,i,j)*(|i-j|==1)
// edge: j=i+1 -> c_local[b,i+1];
//       j=i-1 -> c_local[b,i-1] for 2<=i<=L-2, else c_local[b,i]
//
// Fused kernel: mask prepass folded in via per-warp encoding probe,
// streaming cache hints on the two big streams.

#define ALPHA 0.5f
#define BETA  0.1f
#define NEGV  (-100000.0f)

constexpr int L   = 2048;
constexpr int H   = 16;
constexpr int TPB = 512;   // 512 threads * float4 = 2048 columns

__global__ __launch_bounds__(TPB, 4) void corr_bias_kernel(
    const float* __restrict__ attn,
    const float* __restrict__ c_local,
    const float* __restrict__ c_sink,
    const void*  __restrict__ mraw,
    float* __restrict__ out)
{
    const int r   = blockIdx.x;          // r = b*L + i
    const int b   = r >> 11;             // / L
    const int i   = r & (L - 1);
    const int tid = threadIdx.x;

    // ---- mask encoding probe (warp-uniform, ~free; words are L2-resident) ----
    // Buffer holds 4096 elements: >=1024 int32 words under either encoding,
    // so reading word [tid] (tid<512) is always in-bounds.
    // int32 encoding -> every word is 0/1. byte-packed bools -> a word of 4
    // random 0/1 bytes is >1 with prob 7/8; 32 words all binary: ~8^-32.
    const int*           wi = (const int*)mraw;
    const unsigned char* mb = (const unsigned char*)mraw;
    const unsigned int probe = (unsigned int)wi[tid];
    const bool bytes_enc = (__ballot_sync(0xFFFFFFFFu, probe > 1u) != 0u);

    const int bL = b * L;

    // row mask
    const bool mrow = bytes_enc ? (mb[bL + i] != 0) : (wi[bL + i] != 0);

    const size_t HL      = (size_t)L * (size_t)L;
    const size_t rowbase = (size_t)b * H * HL + (size_t)i * L;

    // ---- fast path: whole (i) row is NEG for every head; attn never read ----
    if (mrow) {
        const float4 negv = make_float4(NEGV, NEGV, NEGV, NEGV);
        #pragma unroll
        for (int h = 0; h < H; h++) {
            __stcs(reinterpret_cast<float4*>(out + rowbase + (size_t)h * HL) + tid, negv);
        }
        return;
    }

    // ---- per-thread bias + column masks for j0..j0+3, computed once ----
    const int   j0 = tid * 4;
    const float si = BETA * c_sink[bL + i];

    const float4 cs = reinterpret_cast<const float4*>(c_sink + (size_t)bL)[tid];

    bool m[4];
    #pragma unroll
    for (int q = 0; q < 4; q++) {
        const int idx = bL + j0 + q;
        m[q] = bytes_enc ? (mb[idx] != 0) : (wi[idx] != 0);
    }

    float bz[4] = { si * cs.x, si * cs.y, si * cs.z, si * cs.w };

    #pragma unroll
    for (int q = 0; q < 4; q++) {
        const int j = j0 + q;
        if (j == i + 1) {
            bz[q] += ALPHA * c_local[bL + j];
        } else if (j == i - 1) {
            // interior rows take the 2nd .set() value c_local[b,i-1];
            // border rows i=1 and i=L-1 keep the 1st .set() value c_local[b,i]
            const int src = (i >= 2 && i <= L - 2) ? (i - 1) : i;
            bz[q] += ALPHA * c_local[bL + src];
        }
    }

    // ---- stream 16 head-rows; bias/mask live in registers ----
    #pragma unroll 4
    for (int h = 0; h < H; h++) {
        const float4 a = __ldcs(reinterpret_cast<const float4*>(attn + rowbase + (size_t)h * HL) + tid);
        float4 o;
        o.x = m[0] ? NEGV : a.x + bz[0];
        o.y = m[1] ? NEGV : a.y + bz[1];
        o.z = m[2] ? NEGV : a.z + bz[2];
        o.w = m[3] ? NEGV : a.w + bz[3];
        __stcs(reinterpret_cast<float4*>(out + rowbase + (size_t)h * HL) + tid, o);
    }
}

extern "C" void kernel_launch(void* const* d_in, const int* in_sizes, int n_in,
                              void* d_out, int out_size)
{
    const float* attn    = (const float*)d_in[0];
    const float* c_local = (const float*)d_in[1];
    const float* c_sink  = (const float*)d_in[2];
    const void*  mraw    = d_in[3];
    float*       out     = (float*)d_out;

    const int n_rows = in_sizes[1];   // B * L = 4096
    corr_bias_kernel<<<n_rows, TPB>>>(attn, c_local, c_sink, mraw, out);
}